// round 4
// baseline (speedup 1.0000x reference)
#include <cuda_runtime.h>
#include <math.h>

#define TPB 128
#define MAXK 128

// Per-block partials: [(b*gx+bx)*4 + {stc,str,cnt,pad}]. Every used slot is
// written each run, so no zeroing kernel is needed.
__device__ float g_part[65536];
// Wrap-around completion counter: returns to 0 after every full run, so graph
// replays are deterministic without an init kernel.
__device__ unsigned g_ctr = 0;

__device__ __forceinline__ float softplusf(float z) {
    return fmaxf(z, 0.f) + log1pf(__expf(-fabsf(z)));  // log(1+exp(z)), stable
}

__device__ __forceinline__ void epilogue(
    const float* __restrict__ prop, const float4* s_g, const float* s_ga,
    int b, int A, int a, float bI, float bS, int bK,
    float& stc, float& strl, float& cnt)
{
    if (a >= A) return;
    const float ts = bI / (bS - bI);   // max IoU (denom = S - inter)
    const float* p = prop + ((size_t)b * A + a) * 6;
    float2 p01 = *reinterpret_cast<const float2*>(p);
    float2 p23 = *reinterpret_cast<const float2*>(p + 2);
    const float x = p[4];
    const float sig = 1.f / (1.f + __expf(-x));
    if (ts >= 0.5f) {
        cnt += 1.f;
        float om = 1.f - sig;
        stc += 0.25f * softplusf(-x) * om * om;     // focal, t=1
        float4 g = s_g[bK];
        float ew = fmaxf(fminf(p01.x + p23.x, g.z) - fmaxf(p01.x, g.x), 0.f);
        float eh = fmaxf(fminf(p01.y + p23.y, g.w) - fmaxf(p01.y, g.y), 0.f);
        float ei = ew * eh;
        float eiou = ei / ((p23.x * p23.y + s_ga[bK]) - ei);
        strl += -__logf(eiou + 0.01f);
    } else if (ts < 0.4f) {
        stc += 0.75f * softplusf(x) * sig * sig;    // focal, t=0
    }
}

template<int KFIX>
__global__ __launch_bounds__(TPB) void loss_kernel(
    const float* __restrict__ prop,     // (B, A, 6)
    const float* __restrict__ anchors,  // (A, 4) xywh
    const float* __restrict__ gt,       // (B, K, 4) xywh
    float* __restrict__ out,
    int A, int Krt, int totalBlocks)
{
    const int K = (KFIX > 0) ? KFIX : Krt;
    __shared__ float4 s_g[MAXK];   // gt boxes xyxy
    __shared__ float  s_ga[MAXK];  // gt areas
    __shared__ float  r0[4], r1[4], r2[4];
    __shared__ int    s_last;
    __shared__ float  s_fin[8][4];

    const int b  = blockIdx.y;
    const int gx = gridDim.x;

    for (int k = threadIdx.x; k < K; k += TPB) {
        const float* g = gt + ((size_t)b * K + k) * 4;
        float x0 = g[0], y0 = g[1], w = g[2], h = g[3];
        s_g[k]  = make_float4(x0, y0, x0 + w, y0 + h);
        s_ga[k] = w * h;
    }
    __syncthreads();

    // two anchors per thread: shared LDS per k, two independent argmax chains
    const int a0 = blockIdx.x * (2 * TPB) + threadIdx.x;
    const int a1 = a0 + TPB;
    const int c0 = min(a0, A - 1);   // clamped load index (mask in epilogue)
    const int c1 = min(a1, A - 1);

    const float4 an0 = reinterpret_cast<const float4*>(anchors)[c0];
    const float4 an1 = reinterpret_cast<const float4*>(anchors)[c1];

    const float ax1_0 = an0.x, ay1_0 = an0.y;
    const float ax2_0 = an0.x + an0.z, ay2_0 = an0.y + an0.w;
    const float areaA0 = an0.z * an0.w;
    const float ax1_1 = an1.x, ay1_1 = an1.y;
    const float ax2_1 = an1.x + an1.z, ay2_1 = an1.y + an1.w;
    const float areaA1 = an1.z * an1.w;

    // Division-free argmax: iou_k > iou_best <=> inter_k*S_best > inter_best*S_k
    // with S_k = areaA + ga[k] = inter + denom. Strict > keeps first max.
    // Single clamp trick: inter = max(w,0)*h. If h<0 then inter<=0 and can
    // never win (rhs bI*S >= 0, strict >). If selected, inter>0 => w,h>0 so
    // the stored value is the true intersection.
    float bI0 = 0.f, bS0 = 1.f; int bK0 = 0;
    float bI1 = 0.f, bS1 = 1.f; int bK1 = 0;

#pragma unroll 4
    for (int k = 0; k < K; k++) {
        float4 g = s_g[k];
        float ga = s_ga[k];
        {
            float w = fminf(ax2_0, g.z) - fmaxf(ax1_0, g.x);
            float h = fminf(ay2_0, g.w) - fmaxf(ay1_0, g.y);
            float inter = fmaxf(w, 0.f) * h;
            float S = areaA0 + ga;
            bool c = inter * bS0 > bI0 * S;
            bI0 = c ? inter : bI0;
            bS0 = c ? S : bS0;
            bK0 = c ? k : bK0;
        }
        {
            float w = fminf(ax2_1, g.z) - fmaxf(ax1_1, g.x);
            float h = fminf(ay2_1, g.w) - fmaxf(ay1_1, g.y);
            float inter = fmaxf(w, 0.f) * h;
            float S = areaA1 + ga;
            bool c = inter * bS1 > bI1 * S;
            bI1 = c ? inter : bI1;
            bS1 = c ? S : bS1;
            bK1 = c ? k : bK1;
        }
    }

    float stc = 0.f, strl = 0.f, cnt = 0.f;
    epilogue(prop, s_g, s_ga, b, A, a0, bI0, bS0, bK0, stc, strl, cnt);
    epilogue(prop, s_g, s_ga, b, A, a1, bI1, bS1, bK1, stc, strl, cnt);

    // block reduction of (stc, strl, cnt)
    const unsigned m = 0xFFFFFFFFu;
#pragma unroll
    for (int o = 16; o; o >>= 1) {
        stc  += __shfl_down_sync(m, stc,  o);
        strl += __shfl_down_sync(m, strl, o);
        cnt  += __shfl_down_sync(m, cnt,  o);
    }
    const int wid = threadIdx.x >> 5, lane = threadIdx.x & 31;
    if (lane == 0) { r0[wid] = stc; r1[wid] = strl; r2[wid] = cnt; }
    __syncthreads();
    if (threadIdx.x == 0) {
        float t0 = 0.f, t1 = 0.f, t2 = 0.f;
#pragma unroll
        for (int i = 0; i < TPB / 32; i++) { t0 += r0[i]; t1 += r1[i]; t2 += r2[i]; }
        int slot = (b * gx + blockIdx.x) * 4;
        g_part[slot + 0] = t0;
        g_part[slot + 1] = t1;
        g_part[slot + 2] = t2;
        __threadfence();
        unsigned old = atomicInc(&g_ctr, (unsigned)(totalBlocks - 1));
        s_last = (old == (unsigned)(totalBlocks - 1)) ? 1 : 0;
    }
    __syncthreads();

    if (s_last) {
        const int B = gridDim.y;
        const int nwarp = TPB / 32;
        if (threadIdx.x < 32) ((float*)s_fin)[threadIdx.x] = 0.f;
        __syncthreads();

        if (B <= nwarp) {
            const int wpb = nwarp / B;            // warps per batch
            const int bb = wid / wpb;
            if (bb < B) {
                float f0 = 0.f, f1 = 0.f, f2 = 0.f;
                for (int blk = lane + 32 * (wid % wpb); blk < gx; blk += 32 * wpb) {
                    int s = (bb * gx + blk) * 4;
                    f0 += g_part[s + 0];
                    f1 += g_part[s + 1];
                    f2 += g_part[s + 2];
                }
#pragma unroll
                for (int o = 16; o; o >>= 1) {
                    f0 += __shfl_down_sync(m, f0, o);
                    f1 += __shfl_down_sync(m, f1, o);
                    f2 += __shfl_down_sync(m, f2, o);
                }
                if (lane == 0) {
                    atomicAdd(&s_fin[bb][0], f0);
                    atomicAdd(&s_fin[bb][1], f1);
                    atomicAdd(&s_fin[bb][2], f2);
                }
            }
            __syncthreads();
            if (threadIdx.x == 0) {
                float t = 0.f;
                for (int bb2 = 0; bb2 < B; bb2++) {
                    float c = s_fin[bb2][2];
                    float safe = (c > 0.f) ? c : 1.f;
                    t += s_fin[bb2][0] / safe;
                    if (c > 0.f) t += s_fin[bb2][1] / safe;
                }
                out[0] = t / (float)B;
            }
        } else if (threadIdx.x == 0) {
            // fallback (B > nwarp): serial, correctness only
            float t = 0.f;
            for (int bb2 = 0; bb2 < B; bb2++) {
                float f0 = 0.f, f1 = 0.f, f2 = 0.f;
                for (int blk = 0; blk < gx; blk++) {
                    int s = (bb2 * gx + blk) * 4;
                    f0 += g_part[s]; f1 += g_part[s + 1]; f2 += g_part[s + 2];
                }
                float safe = (f2 > 0.f) ? f2 : 1.f;
                t += f0 / safe;
                if (f2 > 0.f) t += f1 / safe;
            }
            out[0] = t / (float)B;
        }
    }
}

extern "C" void kernel_launch(void* const* d_in, const int* in_sizes, int n_in,
                              void* d_out, int out_size) {
    const float* prop    = (const float*)d_in[0];  // ss_proposal (B,A,6)
    const float* anchors = (const float*)d_in[1];  // anchors (A,4)
    const float* gt      = (const float*)d_in[2];  // ground_truth (B,K,4)

    const int A = in_sizes[1] / 4;
    const int B = in_sizes[0] / (A * 6);
    const int K = in_sizes[2] / (B * 4);

    const int gx = (A + 2 * TPB - 1) / (2 * TPB);   // 469 for A=120000
    dim3 grid(gx, B);
    const int total = gx * B;

    if (K == 64)
        loss_kernel<64><<<grid, TPB>>>(prop, anchors, gt, (float*)d_out, A, K, total);
    else
        loss_kernel<0><<<grid, TPB>>>(prop, anchors, gt, (float*)d_out, A, K, total);
}